// round 5
// baseline (speedup 1.0000x reference)
#include <cuda_runtime.h>
#include <cuda_bf16.h>
#include <math.h>
#include <stdint.h>

// ---------------------------------------------------------------------------
// B=4, C=180, H=W=256, HEADS=6, hd=30, WS=16, PWS=8, HID=360
// ---------------------------------------------------------------------------
#define HW_   65536
#define M_    262144

typedef __nv_bfloat16 bf16;

// ---------------------------------------------------------------------------
// Scratch
// ---------------------------------------------------------------------------
__device__ bf16  g_ymod[(size_t)M_ * 192];   // LN1+FiLM out / attn out (pad 180..191 = 0)
__device__ bf16  g_qkv [(size_t)M_ * 288];   // q at 0..179, kv at 180..269, pad 270..287
__device__ float g_x1  [(size_t)M_ * 180];   // residual trunk after attn (fp32)
__device__ bf16  g_y2  [(size_t)M_ * 192];   // LN2+FiLM out
__device__ bf16  g_u   [(size_t)M_ * 768];   // pin out (pad 720..767 = 0)
__device__ bf16  g_gt  [(size_t)M_ * 384];   // gated dwconv out (pad 360..383 = 0)
__device__ float g_kvm [4 * 360];
__device__ float g_kvf [4 * 360];
// bf16 weights, K zero-padded
__device__ bf16  g_wqkv [288 * 192];
__device__ bf16  g_wproj[180 * 192];
__device__ bf16  g_wpin [720 * 192];
__device__ bf16  g_wpout[180 * 384];
__device__ float g_bqkv [288];

// ---------------------------------------------------------------------------
// Combined weight conversion (single launch)
// ---------------------------------------------------------------------------
__global__ void wconv_all(const float* __restrict__ wq, const float* __restrict__ wkv,
                          const float* __restrict__ wproj, const float* __restrict__ wpin,
                          const float* __restrict__ wpout,
                          const float* __restrict__ bq, const float* __restrict__ bkv,
                          bf16* __restrict__ dqkv, bf16* __restrict__ dproj,
                          bf16* __restrict__ dpin, bf16* __restrict__ dpout,
                          float* __restrict__ dbqkv)
{
    int i = blockIdx.x * 256 + threadIdx.x;
    if (i < 288 * 192) {
        int n = i / 192, k = i % 192;
        float v = 0.f;
        if (k < 180) {
            if (n < 180)      v = wq[n * 180 + k];
            else if (n < 270) v = wkv[(n - 180) * 180 + k];
        }
        dqkv[i] = __float2bfloat16(v);
        return;
    }
    i -= 288 * 192;
    if (i < 180 * 192) {
        int n = i / 192, k = i % 192;
        dproj[i] = __float2bfloat16(k < 180 ? wproj[n * 180 + k] : 0.f);
        return;
    }
    i -= 180 * 192;
    if (i < 720 * 192) {
        int n = i / 192, k = i % 192;
        dpin[i] = __float2bfloat16(k < 180 ? wpin[n * 180 + k] : 0.f);
        return;
    }
    i -= 720 * 192;
    if (i < 180 * 384) {
        int n = i / 384, k = i % 384;
        dpout[i] = __float2bfloat16(k < 360 ? wpout[n * 360 + k] : 0.f);
        return;
    }
    i -= 180 * 384;
    if (i < 288) {
        float v = 0.f;
        if (i < 180)      v = bq[i];
        else if (i < 270) v = bkv[i - 180];
        dbqkv[i] = v;
    }
}
#define WCONV_ELEMS (288*192 + 180*192 + 720*192 + 180*384 + 288)

// ---------------------------------------------------------------------------
// FiLM params
// ---------------------------------------------------------------------------
__global__ void kvm_kernel(const float* __restrict__ k_v,
                           const float* __restrict__ wa,
                           const float* __restrict__ wf,
                           float* __restrict__ kvm, float* __restrict__ kvf)
{
    int b = blockIdx.x;
    __shared__ float ks[256];
    for (int i = threadIdx.x; i < 256; i += blockDim.x) ks[i] = k_v[b * 256 + i];
    __syncthreads();
    for (int o = threadIdx.x; o < 720; o += blockDim.x) {
        const float* wr = (o < 360) ? (wa + (size_t)o * 256) : (wf + (size_t)(o - 360) * 256);
        float s = 0.f;
        #pragma unroll 8
        for (int k = 0; k < 256; k++) s += ks[k] * wr[k];
        if (o < 360) kvm[b * 360 + o] = s;
        else         kvf[b * 360 + (o - 360)] = s;
    }
}

// ---------------------------------------------------------------------------
// LN1 over C of NCHW + FiLM -> bf16 pixel-major stride 192 (pad zeros)
// ---------------------------------------------------------------------------
__global__ void __launch_bounds__(256) ln1_kernel(
    const float* __restrict__ x, const float* __restrict__ lw,
    const float* __restrict__ lb, const float* __restrict__ kvm,
    bf16* __restrict__ out)
{
    __shared__ float buf[32][181];
    __shared__ float red[2][8][32];
    __shared__ float mean_s[32], rstd_s[32];
    __shared__ float prm[4][180];

    int b  = blockIdx.y;
    int p0 = blockIdx.x * 32;
    int tid = threadIdx.x;
    int px = tid & 31, g = tid >> 5;

    for (int i = tid; i < 180; i += 256) {
        prm[0][i] = lw[i];
        prm[1][i] = lb[i];
        prm[2][i] = kvm[b * 360 + i];
        prm[3][i] = kvm[b * 360 + 180 + i];
    }

    const float* xb = x + (size_t)b * 180 * HW_ + p0 + px;
    float s = 0.f, ss = 0.f;
    for (int c = g; c < 180; c += 8) {
        float v = xb[(size_t)c * HW_];
        buf[px][c] = v;
        s += v; ss += v * v;
    }
    red[0][g][px] = s; red[1][g][px] = ss;
    __syncthreads();
    if (tid < 32) {
        float s2 = 0.f, ss2 = 0.f;
        #pragma unroll
        for (int gg = 0; gg < 8; gg++) { s2 += red[0][gg][tid]; ss2 += red[1][gg][tid]; }
        float mn  = s2 * (1.f / 180.f);
        float var = ss2 * (1.f / 180.f) - mn * mn;
        mean_s[tid] = mn;
        rstd_s[tid] = rsqrtf(var + 1e-5f);
    }
    __syncthreads();

    __nv_bfloat162* ob = (__nv_bfloat162*)(out + ((size_t)b * HW_ + p0) * 192);
    for (int l = tid; l < 32 * 96; l += 256) {
        int p = l / 96, c2 = (l - p * 96) * 2;
        float v0 = 0.f, v1 = 0.f;
        if (c2 < 180) {
            v0 = (buf[p][c2] - mean_s[p]) * rstd_s[p] * prm[0][c2] + prm[1][c2];
            v0 = v0 * prm[2][c2] + prm[3][c2];
            int c3 = c2 + 1;
            v1 = (buf[p][c3] - mean_s[p]) * rstd_s[p] * prm[0][c3] + prm[1][c3];
            v1 = v1 * prm[2][c3] + prm[3][c3];
        }
        ob[p * 96 + (c2 >> 1)] = __floats2bfloat162_rn(v0, v1);
    }
}

// ---------------------------------------------------------------------------
// bf16 tensor-core GEMM (as R3): 128x128 tile, BK=32, mma.m16n8k16,
// cp.async 3-stage, ldmatrix, XOR-swizzled smem, 2 CTAs/SM.
// ---------------------------------------------------------------------------
__device__ __forceinline__ void cpa16(uint32_t dst, const void* src, int sz) {
    asm volatile("cp.async.cg.shared.global [%0], [%1], 16, %2;"
                 :: "r"(dst), "l"(src), "r"(sz));
}
__device__ __forceinline__ void mma_bf16(float* d, const uint32_t* a, const uint32_t* b) {
    asm volatile(
        "mma.sync.aligned.m16n8k16.row.col.f32.bf16.bf16.f32 "
        "{%0,%1,%2,%3},{%4,%5,%6,%7},{%8,%9},{%0,%1,%2,%3};"
        : "+f"(d[0]), "+f"(d[1]), "+f"(d[2]), "+f"(d[3])
        : "r"(a[0]), "r"(a[1]), "r"(a[2]), "r"(a[3]), "r"(b[0]), "r"(b[1]));
}

template<int EPI>
__global__ void __launch_bounds__(256, 2) gemm_bf(
    const bf16* __restrict__ A, const bf16* __restrict__ W,
    const float* __restrict__ bias, void* __restrict__ Cout,
    const float* __restrict__ ex, int N, int NP, int KP, int NKT)
{
    __shared__ __align__(1024) uint8_t sm[3 * 16384];
    uint32_t smb = (uint32_t)__cvta_generic_to_shared(sm);
    const int tid  = threadIdx.x;
    const int m0   = blockIdx.y * 128;
    const int n0   = blockIdx.x * 128;
    const int lane = tid & 31, wid = tid >> 5;
    const int g = lane >> 2, t4 = lane & 3;
    const int wm = wid & 1, wn = wid >> 1;

    const int ra_ = tid >> 1;
    const int ca_ = (tid & 1) * 2;
    const int swr = (ra_ >> 1) & 3;

    auto issue = [&](int kt) {
        int stage = kt % 3;
        uint32_t base = smb + stage * 16384;
        int k0 = kt * 32;
        #pragma unroll
        for (int i = 0; i < 2; i++) {
            int c = ca_ + i;
            uint32_t d = base + ra_ * 64 + ((c ^ swr) * 16);
            cpa16(d, A + (size_t)(m0 + ra_) * KP + k0 + c * 8, 16);
        }
        int n = n0 + ra_;
        const bf16* wrow = W + (size_t)(n < N ? n : 0) * KP + k0;
        int sz = (n < N) ? 16 : 0;
        #pragma unroll
        for (int i = 0; i < 2; i++) {
            int c = ca_ + i;
            uint32_t d = base + 8192 + ra_ * 64 + ((c ^ swr) * 16);
            cpa16(d, wrow + c * 8, sz);
        }
        asm volatile("cp.async.commit_group;");
    };

    float acc[4][4][4];
    #pragma unroll
    for (int i = 0; i < 4; i++)
        #pragma unroll
        for (int j = 0; j < 4; j++)
            #pragma unroll
            for (int e = 0; e < 4; e++) acc[i][j][e] = 0.f;

    issue(0); issue(1);

    const int raf  = lane & 15;
    const int kcf  = lane >> 4;
    const int swzA = (raf >> 1) & 3;
    const int rbf  = lane & 7;
    const int kbf  = (lane >> 3) & 1;
    const int swzB = (rbf >> 1) & 3;

    for (int kt = 0; kt < NKT; kt++) {
        if (kt + 2 < NKT) asm volatile("cp.async.wait_group 1;");
        else              asm volatile("cp.async.wait_group 0;");
        __syncthreads();
        if (kt + 2 < NKT) issue(kt + 2);

        uint32_t baseA = smb + (kt % 3) * 16384;
        uint32_t baseB = baseA + 8192;
        #pragma unroll
        for (int h = 0; h < 2; h++) {
            uint32_t aAddr = baseA + (wm * 64 + raf) * 64 + (((h * 2 + kcf) ^ swzA) * 16);
            uint32_t bAddr = baseB + (wn * 32 + rbf) * 64 + (((h * 2 + kbf) ^ swzB) * 16);
            uint32_t af[4][4], bfr[4][2];
            #pragma unroll
            for (int mt = 0; mt < 4; mt++)
                asm volatile("ldmatrix.sync.aligned.m8n8.x4.shared.b16 {%0,%1,%2,%3},[%4];"
                    : "=r"(af[mt][0]), "=r"(af[mt][1]), "=r"(af[mt][2]), "=r"(af[mt][3])
                    : "r"(aAddr + mt * 16 * 64));
            #pragma unroll
            for (int nt = 0; nt < 4; nt++)
                asm volatile("ldmatrix.sync.aligned.m8n8.x2.shared.b16 {%0,%1},[%2];"
                    : "=r"(bfr[nt][0]), "=r"(bfr[nt][1])
                    : "r"(bAddr + nt * 8 * 64));
            #pragma unroll
            for (int mt = 0; mt < 4; mt++)
                #pragma unroll
                for (int nt = 0; nt < 4; nt++)
                    mma_bf16(acc[mt][nt], af[mt], bfr[nt]);
        }
    }

    #pragma unroll
    for (int mt = 0; mt < 4; mt++) {
        #pragma unroll
        for (int rr = 0; rr < 2; rr++) {
            int m = m0 + wm * 64 + mt * 16 + g + rr * 8;
            int b = m >> 16;
            int p = m & 65535;
            #pragma unroll
            for (int nt = 0; nt < 4; nt++) {
                int n = n0 + wn * 32 + nt * 8 + t4 * 2;
                float v0 = acc[mt][nt][rr * 2 + 0];
                float v1 = acc[mt][nt][rr * 2 + 1];
                if (EPI == 0) {
                    if (n < NP) {
                        if (bias) { if (n < N) v0 += bias[n]; if (n + 1 < N) v1 += bias[n + 1]; }
                        if (n     >= N) v0 = 0.f;
                        if (n + 1 >= N) v1 = 0.f;
                        ((__nv_bfloat162*)Cout)[((size_t)m * NP + n) >> 1] =
                            __floats2bfloat162_rn(v0, v1);
                    }
                } else if (EPI == 1) {
                    if (n < 180) {
                        v0 += bias[n] + ex[((size_t)b * 180 + n) * HW_ + p];
                        ((float*)Cout)[(size_t)m * 180 + n] = v0;
                    }
                    if (n + 1 < 180) {
                        v1 += bias[n + 1] + ex[((size_t)b * 180 + n + 1) * HW_ + p];
                        ((float*)Cout)[(size_t)m * 180 + n + 1] = v1;
                    }
                } else {
                    if (n < 180) {
                        v0 += ex[(size_t)m * 180 + n];
                        ((float*)Cout)[((size_t)b * 180 + n) * HW_ + p] = v0;
                    }
                    if (n + 1 < 180) {
                        v1 += ex[(size_t)m * 180 + n + 1];
                        ((float*)Cout)[((size_t)b * 180 + n + 1) * HW_ + p] = v1;
                    }
                }
            }
        }
    }
}

// ---------------------------------------------------------------------------
// Windowed attention: block = (window, head), 128 threads, 2 queries/thread
// (vertical pair sharing the 2x2 kv group -> same bias row, shared k loads).
// Online softmax in chunks of 16 keys. q/kv from fused qkv buffer (stride 288).
// ---------------------------------------------------------------------------
__global__ void __launch_bounds__(128) attn_kernel(
    const bf16* __restrict__ qkv, const float* __restrict__ rel_table,
    bf16* __restrict__ out)
{
    int head = blockIdx.y;
    int win  = blockIdx.x;
    int b  = win >> 8;
    int wl = win & 255;
    int base_h = (wl >> 4) * 16;
    int base_w = (wl & 15) * 16;

    __shared__ float ksf[64][32];
    __shared__ float vsf[64][32];
    __shared__ float rel_s[225];
    int tid = threadIdx.x;

    for (int i = tid; i < 225; i += 128) rel_s[i] = rel_table[i * 6 + head];

    for (int l = tid; l < 64 * 60; l += 128) {
        int m = l / 60; int r = l % 60; int s = r / 30; int e = r % 30;
        int t = head * 30 + e;
        int i2 = t / 90; int rr = t - i2 * 90; int j2 = rr / 45; int d = rr - j2 * 45;
        int py = base_h + ((m >> 3) << 1) + i2;
        int px = base_w + ((m & 7) << 1) + j2;
        size_t pix = (size_t)b * HW_ + py * 256 + px;
        float v = __bfloat162float(qkv[pix * 288 + 180 + s * 45 + d]);
        if (s == 0) ksf[m][e] = v; else vsf[m][e] = v;
    }
    __syncthreads();

    int ix  = tid & 15;
    int iy0 = (tid >> 4) * 2;
    size_t pix0 = (size_t)b * HW_ + (base_h + iy0) * 256 + base_w + ix;
    size_t pix1 = pix0 + 256;

    float2 qa[15], qb2[15];
    {
        const __nv_bfloat162* p0 = (const __nv_bfloat162*)(qkv + pix0 * 288 + head * 30);
        const __nv_bfloat162* p1 = (const __nv_bfloat162*)(qkv + pix1 * 288 + head * 30);
        #pragma unroll
        for (int e = 0; e < 15; e++) {
            __nv_bfloat162 h0 = p0[e], h1 = p1[e];
            qa[e]  = make_float2(__bfloat162float(h0.x), __bfloat162float(h0.y));
            qb2[e] = make_float2(__bfloat162float(h1.x), __bfloat162float(h1.y));
        }
    }

    const float scale = 0.1825741858350554f;   // 30^-0.5
    int qy = tid >> 4, qx = ix >> 1;

    float rm0 = -1e30f, rs0 = 0.f, rm1 = -1e30f, rs1 = 0.f;
    float ac0[30], ac1[30];
    #pragma unroll
    for (int e = 0; e < 30; e++) { ac0[e] = 0.f; ac1[e] = 0.f; }

    #pragma unroll
    for (int c0 = 0; c0 < 64; c0 += 16) {
        float lg0[16], lg1[16];
        float cm0 = -1e30f, cm1 = -1e30f;
        #pragma unroll
        for (int j = 0; j < 16; j++) {
            int m = c0 + j;
            const float2* krow = (const float2*)ksf[m];
            float d0 = 0.f, d1 = 0.f;
            #pragma unroll
            for (int e = 0; e < 15; e++) {
                float2 k2 = krow[e];
                d0 += qa[e].x  * k2.x + qa[e].y  * k2.y;
                d1 += qb2[e].x * k2.x + qb2[e].y * k2.y;
            }
            int dy = qy - (m >> 3) + 7;
            int dx = qx - (m & 7) + 7;
            float bi = rel_s[dy * 15 + dx];
            float v0 = d0 * scale + bi;
            float v1 = d1 * scale + bi;
            lg0[j] = v0; lg1[j] = v1;
            cm0 = fmaxf(cm0, v0);
            cm1 = fmaxf(cm1, v1);
        }
        float nm0 = fmaxf(rm0, cm0);
        float nm1 = fmaxf(rm1, cm1);
        float f0 = __expf(rm0 - nm0);
        float f1 = __expf(rm1 - nm1);
        rs0 *= f0; rs1 *= f1;
        #pragma unroll
        for (int e = 0; e < 30; e++) { ac0[e] *= f0; ac1[e] *= f1; }
        #pragma unroll
        for (int j = 0; j < 16; j++) {
            float p0 = __expf(lg0[j] - nm0);
            float p1 = __expf(lg1[j] - nm1);
            rs0 += p0; rs1 += p1;
            const float2* vrow = (const float2*)vsf[c0 + j];
            #pragma unroll
            for (int e = 0; e < 15; e++) {
                float2 v2 = vrow[e];
                ac0[2 * e]     += p0 * v2.x;
                ac0[2 * e + 1] += p0 * v2.y;
                ac1[2 * e]     += p1 * v2.x;
                ac1[2 * e + 1] += p1 * v2.y;
            }
        }
        rm0 = nm0; rm1 = nm1;
    }
    float i0 = 1.0f / rs0, i1 = 1.0f / rs1;
    __nv_bfloat162* o0 = (__nv_bfloat162*)(out + pix0 * 192 + head * 30);
    __nv_bfloat162* o1 = (__nv_bfloat162*)(out + pix1 * 192 + head * 30);
    #pragma unroll
    for (int e = 0; e < 15; e++) {
        o0[e] = __floats2bfloat162_rn(ac0[2 * e] * i0, ac0[2 * e + 1] * i0);
        o1[e] = __floats2bfloat162_rn(ac1[2 * e] * i1, ac1[2 * e + 1] * i1);
    }
}

// ---------------------------------------------------------------------------
// LN2 over pixel-major fp32 x1 + FiLM -> bf16 y2 (stride 192, pad zeros)
// ---------------------------------------------------------------------------
__global__ void __launch_bounds__(256) ln2_kernel(
    const float* __restrict__ x1, const float* __restrict__ lw,
    const float* __restrict__ lb, const float* __restrict__ kvf,
    bf16* __restrict__ out)
{
    int warp = threadIdx.x >> 5, lane = threadIdx.x & 31;
    size_t pix = (size_t)blockIdx.x * 8 + warp;
    int b = (int)(pix >> 16);
    const float* xp = x1 + pix * 180;

    float2 vals[3];
    float s = 0.f, ss = 0.f;
    #pragma unroll
    for (int i = 0; i < 3; i++) {
        int c2 = (lane + i * 32) * 2;
        float2 v = make_float2(0.f, 0.f);
        if (c2 < 180) v = *(const float2*)(xp + c2);
        vals[i] = v;
        s  += v.x + v.y;
        ss += v.x * v.x + v.y * v.y;
    }
    #pragma unroll
    for (int off = 16; off > 0; off >>= 1) {
        s  += __shfl_xor_sync(0xffffffffu, s,  off);
        ss += __shfl_xor_sync(0xffffffffu, ss, off);
    }
    float mean = s * (1.f / 180.f);
    float var  = ss * (1.f / 180.f) - mean * mean;
    float rstd = rsqrtf(var + 1e-5f);

    __nv_bfloat162* op = (__nv_bfloat162*)(out + pix * 192);
    #pragma unroll
    for (int i = 0; i < 3; i++) {
        int c2 = (lane + i * 32) * 2;
        float v0 = 0.f, v1 = 0.f;
        if (c2 < 180) {
            v0 = (vals[i].x - mean) * rstd * lw[c2] + lb[c2];
            v0 = v0 * kvf[b * 360 + c2] + kvf[b * 360 + 180 + c2];
            v1 = (vals[i].y - mean) * rstd * lw[c2 + 1] + lb[c2 + 1];
            v1 = v1 * kvf[b * 360 + c2 + 1] + kvf[b * 360 + 180 + c2 + 1];
        }
        op[c2 >> 1] = __floats2bfloat162_rn(v0, v1);
    }
}

// ---------------------------------------------------------------------------
// Depthwise 3x3 + exact-GELU gate. 48-channel chunks, uint2 (4ch) loads,
// both halves staged in one pass. u bf16 (stride 768) -> gt bf16 (stride 384).
// Channels >= 360 write 0 (the K-pad for pout).
// ---------------------------------------------------------------------------
__global__ void __launch_bounds__(384) dwconv_kernel(
    const bf16* __restrict__ u, const float* __restrict__ wdw,
    bf16* __restrict__ g)
{
    const int CC = 48;
    __shared__ float t1[10][10][CC];
    __shared__ float t2[10][10][CC];

    int chunk = blockIdx.z & 7;
    int b     = blockIdx.z >> 3;
    int c0 = chunk * CC;
    int h0 = blockIdx.y * 8, w0 = blockIdx.x * 8;
    int ch = threadIdx.x;        // 0..47
    int xcol = threadIdx.y;      // 0..7
    int tid = threadIdx.y * CC + threadIdx.x;

    for (int l = tid; l < 1200; l += 384) {
        int cc4 = (l % 12) * 4;
        int pp  = l / 12;
        int py = h0 + pp / 10 - 1;
        int px = w0 + pp % 10 - 1;
        float f1[4] = {0.f, 0.f, 0.f, 0.f};
        float f2[4] = {0.f, 0.f, 0.f, 0.f};
        if (py >= 0 && py < 256 && px >= 0 && px < 256) {
            const bf16* base = u + ((size_t)b * HW_ + py * 256 + px) * 768;
            uint2 r1 = *(const uint2*)(base + c0 + cc4);
            uint2 r2 = *(const uint2*)(base + c0 + 360 + cc4);
            __nv_bfloat162 h;
            h = *(__nv_bfloat162*)&r1.x; f1[0] = __bfloat162float(h.x); f1[1] = __bfloat162float(h.y);
            h = *(__nv_bfloat162*)&r1.y; f1[2] = __bfloat162float(h.x); f1[3] = __bfloat162float(h.y);
            h = *(__nv_bfloat162*)&r2.x; f2[0] = __bfloat162float(h.x); f2[1] = __bfloat162float(h.y);
            h = *(__nv_bfloat162*)&r2.y; f2[2] = __bfloat162float(h.x); f2[3] = __bfloat162float(h.y);
        }
        int ty = pp / 10, tx = pp % 10;
        #pragma unroll
        for (int e = 0; e < 4; e++) {
            t1[ty][tx][cc4 + e] = f1[e];
            t2[ty][tx][cc4 + e] = f2[e];
        }
    }
    __syncthreads();

    int c = c0 + ch;
    bool act = (c < 360);
    float w1[9], w2[9];
    #pragma unroll
    for (int r = 0; r < 9; r++) {
        w1[r] = act ? wdw[(size_t)c * 9 + r] : 0.f;
        w2[r] = act ? wdw[(size_t)(c + 360) * 9 + r] : 0.f;
    }
    #pragma unroll
    for (int oy = 0; oy < 8; oy++) {
        float a1 = 0.f, a2 = 0.f;
        #pragma unroll
        for (int ky = 0; ky < 3; ky++)
            #pragma unroll
            for (int kx = 0; kx < 3; kx++) {
                a1 += t1[oy + ky][xcol + kx][ch] * w1[ky * 3 + kx];
                a2 += t2[oy + ky][xcol + kx][ch] * w2[ky * 3 + kx];
            }
        float r = 0.f;
        if (act) {
            float gl = 0.5f * a1 * (1.f + erff(a1 * 0.70710678118654752f));
            r = gl * a2;
        }
        g[((size_t)b * HW_ + (h0 + oy) * 256 + w0 + xcol) * 384 + c] = __float2bfloat16(r);
    }
}

// ---------------------------------------------------------------------------
// Launch sequence
// ---------------------------------------------------------------------------
extern "C" void kernel_launch(void* const* d_in, const int* in_sizes, int n_in,
                              void* d_out, int out_size)
{
    const float* x           = (const float*)d_in[0];
    const float* k_v         = (const float*)d_in[1];
    const float* ln1_w       = (const float*)d_in[2];
    const float* ln1_b       = (const float*)d_in[3];
    const float* ln2_w       = (const float*)d_in[4];
    const float* ln2_b       = (const float*)d_in[5];
    const float* w_kern_attn = (const float*)d_in[6];
    const float* rel_table   = (const float*)d_in[7];
    const float* w_kv        = (const float*)d_in[8];
    const float* b_kv        = (const float*)d_in[9];
    const float* w_q         = (const float*)d_in[10];
    const float* b_q         = (const float*)d_in[11];
    const float* w_proj      = (const float*)d_in[12];
    const float* b_proj      = (const float*)d_in[13];
    const float* w_kern_ffn  = (const float*)d_in[14];
    const float* w_pin       = (const float*)d_in[15];
    const float* w_dw        = (const float*)d_in[16];
    const float* w_pout      = (const float*)d_in[17];
    float* out = (float*)d_out;

    float *x1, *kvm, *kvf, *bqkv;
    bf16 *ymod, *qkv, *y2, *u, *gt, *wqkv, *wproj, *wpin, *wpout;
    cudaGetSymbolAddress((void**)&ymod,  g_ymod);
    cudaGetSymbolAddress((void**)&qkv,   g_qkv);
    cudaGetSymbolAddress((void**)&x1,    g_x1);
    cudaGetSymbolAddress((void**)&y2,    g_y2);
    cudaGetSymbolAddress((void**)&u,     g_u);
    cudaGetSymbolAddress((void**)&gt,    g_gt);
    cudaGetSymbolAddress((void**)&kvm,   g_kvm);
    cudaGetSymbolAddress((void**)&kvf,   g_kvf);
    cudaGetSymbolAddress((void**)&wqkv,  g_wqkv);
    cudaGetSymbolAddress((void**)&wproj, g_wproj);
    cudaGetSymbolAddress((void**)&wpin,  g_wpin);
    cudaGetSymbolAddress((void**)&wpout, g_wpout);
    cudaGetSymbolAddress((void**)&bqkv,  g_bqkv);

    wconv_all<<<(WCONV_ELEMS + 255) / 256, 256>>>(
        w_q, w_kv, w_proj, w_pin, w_pout, b_q, b_kv,
        wqkv, wproj, wpin, wpout, bqkv);

    kvm_kernel<<<4, 256>>>(k_v, w_kern_attn, w_kern_ffn, kvm, kvf);
    ln1_kernel<<<dim3(2048, 4), 256>>>(x, ln1_w, ln1_b, kvm, ymod);

    // fused q+kv projection (N=270, stride 288)
    gemm_bf<0><<<dim3(3, 2048), 256>>>(ymod, wqkv, bqkv, qkv, nullptr, 270, 288, 192, 6);

    attn_kernel<<<dim3(1024, 6), 128>>>(qkv, rel_table, ymod);

    gemm_bf<1><<<dim3(2, 2048), 256>>>(ymod, wproj, b_proj, x1, x, 180, 180, 192, 6);

    ln2_kernel<<<32768, 256>>>(x1, ln2_w, ln2_b, kvf, y2);

    gemm_bf<0><<<dim3(6, 2048), 256>>>(y2, wpin, nullptr, u, nullptr, 720, 768, 192, 6);

    dwconv_kernel<<<dim3(32, 32, 32), dim3(48, 8)>>>(u, w_dw, gt);

    gemm_bf<2><<<dim3(2, 2048), 256>>>(gt, wpout, nullptr, out, x1, 180, 180, 384, 12);
}